// round 7
// baseline (speedup 1.0000x reference)
#include <cuda_runtime.h>
#include <cuda_bf16.h>

#define N_NODES 384
#define HEIGHT  60
#define CCH     128
#define N_LAYERS 4
#define NODE_SZ (CCH * HEIGHT)          // 7680 floats per node
#define ES_OFF  (3 * NODE_SZ)
#define DYN_F   (ES_OFF + 8 * CCH)
#define DYN_SMEM (DYN_F * 4)            // ~94 KB (edge kernel)

// ---------------- device scratch ----------------
__device__ __align__(16) float g_y[N_NODES * 2 * NODE_SZ];   // [n][a/b][r][h] fp32 gemm out
// B fragments (bf16 hi/lo), per node padded 128x64: [node][ks8][nf8][lane32][breg2][half2]
__device__ __align__(16) __nv_bfloat16 XBh[N_NODES * 8192];  // zero-init covers n-padding
__device__ __align__(16) __nv_bfloat16 XBl[N_NODES * 8192];
// A fragments (bf16 hi/lo): [l][mt16][ks8][lane32][4regs] u32
__device__ __align__(16) unsigned WFh[N_LAYERS * 16384];
__device__ __align__(16) unsigned WFl[N_LAYERS * 16384];
__device__ float g_M[N_LAYERS * CCH * 6];
__device__ int   g_nbr[N_NODES * 16];
__device__ int   g_deg[N_NODES];

// ---------------- helpers ----------------
__device__ __forceinline__ unsigned pack_bf16x2(float a, float b) {
    __nv_bfloat162 p = __floats2bfloat162_rn(a, b);   // a -> low half
    return *reinterpret_cast<unsigned*>(&p);
}
// bf16 element index into XB for logical element (c, h) of a node
__device__ __forceinline__ int xb_idx(int node, int c, int h) {
    int ks = c >> 4, kl = c & 15;
    int breg = kl >> 3, rem = kl & 7;
    int t = rem >> 1, half = rem & 1;
    int nf = h >> 3, g = h & 7;
    int lane = g * 4 + t;
    return ((((node * 8 + ks) * 8 + nf) * 32 + lane) * 2 + breg) * 2 + half;
}
__device__ __forceinline__ void split_store(int idx, float v) {
    __nv_bfloat16 hi = __float2bfloat16(v);
    XBh[idx] = hi;
    XBl[idx] = __float2bfloat16(v - __bfloat162float(hi));
}
__device__ __forceinline__ void mma16816(float* d, const uint4& a, const uint2& b) {
    asm volatile(
        "mma.sync.aligned.m16n8k16.row.col.f32.bf16.bf16.f32 "
        "{%0,%1,%2,%3}, {%4,%5,%6,%7}, {%8,%9}, {%0,%1,%2,%3};"
        : "+f"(d[0]), "+f"(d[1]), "+f"(d[2]), "+f"(d[3])
        : "r"(a.x), "r"(a.y), "r"(a.z), "r"(a.w), "r"(b.x), "r"(b.y));
}
__device__ __forceinline__ void cp16(unsigned dst, const float* src) {
    asm volatile("cp.async.cg.shared.global [%0], [%1], 16;" :: "r"(dst), "l"(src));
}
__device__ __forceinline__ void prefetch_node(float* buf, const float* __restrict__ src, int tid) {
    unsigned b = (unsigned)__cvta_generic_to_shared(buf);
    for (int i = tid; i < NODE_SZ / 4; i += 512)
        cp16(b + i * 16, src + i * 4);
    asm volatile("cp.async.commit_group;");
}

// ---------------- setup: block 0 = CSR, blocks 1..4 = weight frag packing -----
__global__ void setup_kernel(const int* __restrict__ ei, int E,
                             const float* __restrict__ conv_w,
                             const float* __restrict__ edge_w,
                             const float* __restrict__ edge_b) {
    int tid = threadIdx.x;
    if (blockIdx.x == 0) {
        int n = tid;
        if (n >= N_NODES) return;
        const int* dst = ei + E;
        int cnt = 0;
        for (int e = 0; e < E; e++) {
            if (dst[e] == n) {
                if (cnt < 8) g_nbr[n * 16 + cnt] = e;
                cnt++;
            }
        }
        g_deg[n] = cnt < 8 ? cnt : 8;
        return;
    }
    int l = blockIdx.x - 1;
    const float* cw = conv_w + l * (CCH * 3 * CCH);
    // A fragments: folded weight A[m][k]; m<128: W1-W2 ; m>=128: W2
    for (int i = tid; i < 16384; i += 384) {
        int j = i & 3, lane = (i >> 2) & 31, ks = (i >> 7) & 7, mt = i >> 10;
        int g = lane >> 2, t = lane & 3;
        int m = (mt << 4) + g + ((j & 1) << 3);
        int k = (ks << 4) + (t << 1) + ((j >> 1) << 3);
        float v0, v1;
        if (m < 128) {
            v0 = cw[m * 384 + k] - cw[m * 384 + 128 + k];
            v1 = cw[m * 384 + k + 1] - cw[m * 384 + 128 + k + 1];
        } else {
            v0 = cw[(m - 128) * 384 + 128 + k];
            v1 = cw[(m - 128) * 384 + 128 + k + 1];
        }
        float h0 = __bfloat162float(__float2bfloat16(v0));
        float h1 = __bfloat162float(__float2bfloat16(v1));
        WFh[l * 16384 + i] = pack_bf16x2(h0, h1);
        WFl[l * 16384 + i] = pack_bf16x2(v0 - h0, v1 - h1);
    }
    if (tid < CCH) {
        int c = tid;
        const float* cw3 = cw + c * 384 + 256;
        const float* ewl = edge_w + l * (CCH * 5);
        const float* ebl = edge_b + l * CCH;
        float m0 = 0.f, m1 = 0.f, m2 = 0.f, m3 = 0.f, m4 = 0.f, m5 = 0.f;
        for (int k = 0; k < CCH; k++) {
            float w = cw3[k];
            m0 += w * ewl[k * 5 + 0];
            m1 += w * ewl[k * 5 + 1];
            m2 += w * ewl[k * 5 + 2];
            m3 += w * ewl[k * 5 + 3];
            m4 += w * ewl[k * 5 + 4];
            m5 += w * ebl[k];
        }
        float* Mp = g_M + l * (CCH * 6) + c * 6;
        Mp[0] = m0; Mp[1] = m1; Mp[2] = m2; Mp[3] = m3; Mp[4] = m4; Mp[5] = m5;
    }
}

// ---------------- layer-0 input -> B fragments -------------------------------
__global__ __launch_bounds__(512)
void convert_kernel(const float* __restrict__ x0) {
    int node = blockIdx.x, tid = threadIdx.x;
    const float* xn = x0 + (size_t)node * NODE_SZ;
#pragma unroll
    for (int it = 0; it < 15; it++) {
        int i = tid + (it << 9);
        int c = i / HEIGHT, h = i - c * HEIGHT;
        split_store(xb_idx(node, c, h), xn[i]);
    }
}

// ---------------- GEMM via mma.sync bf16 (split, 3 terms) --------------------
// grid = 384 nodes x 4 mgroups; block 128 (4 warps: 2 mtiles x 4 nfrags each).
__global__ __launch_bounds__(128)
void gemm_mma_kernel(int l) {
    int tid = threadIdx.x, w = tid >> 5, lane = tid & 31;
    int node = blockIdx.x >> 2, mg = blockIdx.x & 3;
    int mt0 = mg * 4 + (w >> 1) * 2;       // this warp: mtiles mt0, mt0+1
    int nh = w & 1;                        // n-frags nh*4 .. nh*4+3
    int g = lane >> 2, t = lane & 3;

    const uint4* WAh = reinterpret_cast<const uint4*>(WFh);
    const uint4* WAl = reinterpret_cast<const uint4*>(WFl);
    const uint2* XB2h = reinterpret_cast<const uint2*>(XBh);
    const uint2* XB2l = reinterpret_cast<const uint2*>(XBl);

    float acc[2][4][4];
#pragma unroll
    for (int mi = 0; mi < 2; mi++)
#pragma unroll
        for (int nf = 0; nf < 4; nf++)
#pragma unroll
            for (int q = 0; q < 4; q++) acc[mi][nf][q] = 0.f;

#pragma unroll
    for (int ks = 0; ks < 8; ks++) {
        uint4 Ah[2], Al[2];
#pragma unroll
        for (int mi = 0; mi < 2; mi++) {
            int ai = ((l * 16 + mt0 + mi) * 8 + ks) * 32 + lane;
            Ah[mi] = WAh[ai];
            Al[mi] = WAl[ai];
        }
        uint2 Bh[4], Bl[4];
#pragma unroll
        for (int nf = 0; nf < 4; nf++) {
            int bi = ((node * 8 + ks) * 8 + nh * 4 + nf) * 32 + lane;
            Bh[nf] = XB2h[bi];
            Bl[nf] = XB2l[bi];
        }
#pragma unroll
        for (int mi = 0; mi < 2; mi++)
#pragma unroll
            for (int nf = 0; nf < 4; nf++) {
                mma16816(acc[mi][nf], Ah[mi], Bh[nf]);
                mma16816(acc[mi][nf], Ah[mi], Bl[nf]);
                mma16816(acc[mi][nf], Al[mi], Bh[nf]);
            }
    }

#pragma unroll
    for (int mi = 0; mi < 2; mi++)
#pragma unroll
        for (int nf = 0; nf < 4; nf++) {
            int m = (mt0 + mi) * 16 + g;
            int h0 = (nh * 4 + nf) * 8 + 2 * t;
            if (h0 < HEIGHT) {
                size_t base = ((size_t)node * 2 + (m >> 7)) * NODE_SZ;
                float* p0 = g_y + base + (m & 127) * HEIGHT + h0;
                *(float2*)p0 = make_float2(acc[mi][nf][0], acc[mi][nf][1]);
                float* p1 = g_y + base + ((m + 8) & 127) * HEIGHT + h0;
                *(float2*)p1 = make_float2(acc[mi][nf][2], acc[mi][nf][3]);
            }
        }
}

// ---------------- edge(l): per-dst CTA, 512 threads ---------------------------
__global__ __launch_bounds__(512, 2)
void edge_kernel(const float* __restrict__ ea,
                 const float* __restrict__ lng,
                 const float* __restrict__ lnb,
                 const int* __restrict__ ei,
                 float* __restrict__ dout, int l) {
    extern __shared__ float sm[];
    float* es_all = sm + ES_OFF;
    __shared__ float red[32];

    int n = blockIdx.x, tid = threadIdx.x;
    const float* gl = lng + l * NODE_SZ;
    const float* bl = lnb + l * NODE_SZ;
    int deg = g_deg[n];

    {
        int s0 = ei[g_nbr[n * 16]];
        prefetch_node(sm, g_y + (size_t)(2 * s0 + 1) * NODE_SZ, tid);
    }

    const float* yan = g_y + (size_t)(2 * n) * NODE_SZ;
    float ya[15], acc[15];
#pragma unroll
    for (int it = 0; it < 15; it++) {
        ya[it] = yan[tid + (it << 9)];
        acc[it] = 0.f;
    }
    for (int idx = tid; idx < deg * CCH; idx += 512) {
        int j = idx >> 7, c = idx & 127;
        int e = g_nbr[n * 16 + j];
        const float* Mp = g_M + l * (CCH * 6) + c * 6;
        const float* eap = ea + e * 5;
        es_all[idx] = fmaf(Mp[0], eap[0], fmaf(Mp[1], eap[1], fmaf(Mp[2], eap[2],
                      fmaf(Mp[3], eap[3], fmaf(Mp[4], eap[4], Mp[5])))));
    }

    int bj = 0;
    for (int j = 0; j < deg; j++) {
        if (j + 1 < deg) {
            int s1i = ei[g_nbr[n * 16 + j + 1]];
            int bn = bj + 1; if (bn == 3) bn = 0;
            prefetch_node(sm + bn * NODE_SZ, g_y + (size_t)(2 * s1i + 1) * NODE_SZ, tid);
            asm volatile("cp.async.wait_group 1;");
        } else {
            asm volatile("cp.async.wait_group 0;");
        }
        __syncthreads();   // slot bj (+ es_all on j==0) visible; 3-slot ring safety

        const float* bf = sm + bj * NODE_SZ;
        const float* esj = es_all + j * CCH;
        float s1 = 0.f, s2 = 0.f;
#pragma unroll
        for (int it = 0; it < 15; it++) {
            int i = tid + (it << 9);
            float v = ya[it] + bf[i] + esj[i / HEIGHT];
            s1 += v;
            s2 += v * v;
        }
#pragma unroll
        for (int o = 16; o; o >>= 1) {
            s1 += __shfl_xor_sync(0xffffffffu, s1, o);
            s2 += __shfl_xor_sync(0xffffffffu, s2, o);
        }
        if ((tid & 31) == 0) { red[tid >> 5] = s1; red[16 + (tid >> 5)] = s2; }
        __syncthreads();
        float a = 0.f, b2 = 0.f;
#pragma unroll
        for (int w = 0; w < 16; w++) { a += red[w]; b2 += red[16 + w]; }
        float mu = a * (1.f / (float)NODE_SZ);
        float rs = rsqrtf(b2 * (1.f / (float)NODE_SZ) - mu * mu + 1e-5f);
#pragma unroll
        for (int it = 0; it < 15; it++) {
            int i = tid + (it << 9);
            float v = ya[it] + bf[i] + esj[i / HEIGHT];
            float o2 = (v - mu) * rs * gl[i] + bl[i];
            acc[it] += fmaxf(o2, 0.f);
        }
        bj++; if (bj == 3) bj = 0;
    }

    if (l == 3) {
        float* on = dout + (size_t)n * NODE_SZ;
#pragma unroll
        for (int it = 0; it < 15; it++)
            on[tid + (it << 9)] = acc[it];
    } else {
#pragma unroll
        for (int it = 0; it < 15; it++) {
            int i = tid + (it << 9);
            int c = i / HEIGHT, h = i - c * HEIGHT;
            split_store(xb_idx(n, c, h), acc[it]);
        }
    }
}

// ---------------- launch -----------------------------------------------------
extern "C" void kernel_launch(void* const* d_in, const int* in_sizes, int n_in,
                              void* d_out, int out_size) {
    const float* x   = (const float*)d_in[0];
    const float* ea  = (const float*)d_in[1];
    const float* ew  = (const float*)d_in[2];
    const float* eb  = (const float*)d_in[3];
    const float* cw  = (const float*)d_in[4];
    const float* lng = (const float*)d_in[5];
    const float* lnb = (const float*)d_in[6];
    const int*   ei  = (const int*)d_in[7];
    float* out = (float*)d_out;
    int E = in_sizes[7] / 2;

    cudaFuncSetAttribute(edge_kernel, cudaFuncAttributeMaxDynamicSharedMemorySize, DYN_SMEM);

    setup_kernel<<<5, 384>>>(ei, E, cw, ew, eb);
    convert_kernel<<<N_NODES, 512>>>(x);
    for (int l = 0; l < N_LAYERS; l++) {
        gemm_mma_kernel<<<N_NODES * 4, 128>>>(l);
        edge_kernel<<<N_NODES, 512, DYN_SMEM>>>(ea, lng, lnb, ei, out, l);
    }
}

// round 8
// speedup vs baseline: 1.3855x; 1.3855x over previous
#include <cuda_runtime.h>
#include <cuda_bf16.h>

#define N_NODES 384
#define HEIGHT  60
#define CCH     128
#define N_LAYERS 4
#define NODE_SZ (CCH * HEIGHT)          // 7680 floats per node
#define ES_OFF  (3 * NODE_SZ)
#define DYN_F   (ES_OFF + 8 * CCH)
#define DYN_SMEM (DYN_F * 4)            // ~94 KB (edge kernel)

// ---------------- device scratch ----------------
__device__ __align__(16) float g_y[N_NODES * 2 * NODE_SZ];   // [n][a/b][r][h] fp32 gemm out
// B fragments (bf16 hi/lo) per node: u32 slot s = ks*512 + nf*64 + lane*2 + breg
__device__ __align__(16) unsigned XBh[N_NODES * 4096];
__device__ __align__(16) unsigned XBl[N_NODES * 4096];
// A fragments (bf16 hi/lo): [l][mt16][ks8][lane32][4regs] u32
__device__ __align__(16) unsigned WFh[N_LAYERS * 16384];
__device__ __align__(16) unsigned WFl[N_LAYERS * 16384];
__device__ float g_M[N_LAYERS * CCH * 6];
__device__ int   g_nbr[N_NODES * 16];
__device__ int   g_deg[N_NODES];

// ---------------- helpers ----------------
__device__ __forceinline__ unsigned pack_bf16x2(float a, float b) {
    __nv_bfloat162 p = __floats2bfloat162_rn(a, b);   // a -> low half
    return *reinterpret_cast<unsigned*>(&p);
}
// permute linear (c,h) buffer in smem -> coalesced fragment stores for one node
__device__ __forceinline__ void frag_store(const float* lin, int node, int tid, int nthr) {
    unsigned* XH = XBh + node * 4096;
    unsigned* XL = XBl + node * 4096;
    for (int s = tid; s < 4096; s += nthr) {
        int breg = s & 1, lane = (s >> 1) & 31, nf = (s >> 6) & 7, ks = s >> 9;
        int c0 = ks * 16 + breg * 8 + (lane & 3) * 2;
        int h = nf * 8 + (lane >> 2);
        float v0 = 0.f, v1 = 0.f;
        if (h < HEIGHT) {
            v0 = lin[c0 * HEIGHT + h];
            v1 = lin[(c0 + 1) * HEIGHT + h];
        }
        float h0 = __bfloat162float(__float2bfloat16(v0));
        float h1 = __bfloat162float(__float2bfloat16(v1));
        XH[s] = pack_bf16x2(h0, h1);
        XL[s] = pack_bf16x2(v0 - h0, v1 - h1);
    }
}
__device__ __forceinline__ void mma16816(float* d, const uint4& a, const uint2& b) {
    asm volatile(
        "mma.sync.aligned.m16n8k16.row.col.f32.bf16.bf16.f32 "
        "{%0,%1,%2,%3}, {%4,%5,%6,%7}, {%8,%9}, {%0,%1,%2,%3};"
        : "+f"(d[0]), "+f"(d[1]), "+f"(d[2]), "+f"(d[3])
        : "r"(a.x), "r"(a.y), "r"(a.z), "r"(a.w), "r"(b.x), "r"(b.y));
}
__device__ __forceinline__ void cp16(unsigned dst, const float* src) {
    asm volatile("cp.async.cg.shared.global [%0], [%1], 16;" :: "r"(dst), "l"(src));
}
__device__ __forceinline__ void prefetch_node(float* buf, const float* __restrict__ src, int tid) {
    unsigned b = (unsigned)__cvta_generic_to_shared(buf);
    for (int i = tid; i < NODE_SZ / 4; i += 512)
        cp16(b + i * 16, src + i * 4);
    asm volatile("cp.async.commit_group;");
}

// ---------------- setup: blk0 = CSR, blk1..4 = weights, blk5.. = x0 convert ---
__global__ void setup_kernel(const int* __restrict__ ei, int E,
                             const float* __restrict__ conv_w,
                             const float* __restrict__ edge_w,
                             const float* __restrict__ edge_b,
                             const float* __restrict__ x0) {
    __shared__ float lin[NODE_SZ];
    int tid = threadIdx.x;
    if (blockIdx.x == 0) {
        int n = tid;
        if (n >= N_NODES) return;
        const int* dst = ei + E;
        int cnt = 0;
        for (int e = 0; e < E; e++) {
            if (dst[e] == n) {
                if (cnt < 8) g_nbr[n * 16 + cnt] = e;
                cnt++;
            }
        }
        g_deg[n] = cnt < 8 ? cnt : 8;
        return;
    }
    if (blockIdx.x >= 5) {   // layer-0 input -> B fragments
        int node = blockIdx.x - 5;
        const float* xn = x0 + (size_t)node * NODE_SZ;
        for (int i = tid; i < NODE_SZ; i += 384)
            lin[i] = xn[i];
        __syncthreads();
        frag_store(lin, node, tid, 384);
        return;
    }
    int l = blockIdx.x - 1;
    const float* cw = conv_w + l * (CCH * 3 * CCH);
    // A fragments: folded weight A[m][k]; m<128: W1-W2 ; m>=128: W2
    for (int i = tid; i < 16384; i += 384) {
        int j = i & 3, lane = (i >> 2) & 31, ks = (i >> 7) & 7, mt = i >> 10;
        int g = lane >> 2, t = lane & 3;
        int m = (mt << 4) + g + ((j & 1) << 3);
        int k = (ks << 4) + (t << 1) + ((j >> 1) << 3);
        float v0, v1;
        if (m < 128) {
            v0 = cw[m * 384 + k] - cw[m * 384 + 128 + k];
            v1 = cw[m * 384 + k + 1] - cw[m * 384 + 128 + k + 1];
        } else {
            v0 = cw[(m - 128) * 384 + 128 + k];
            v1 = cw[(m - 128) * 384 + 128 + k + 1];
        }
        float h0 = __bfloat162float(__float2bfloat16(v0));
        float h1 = __bfloat162float(__float2bfloat16(v1));
        WFh[l * 16384 + i] = pack_bf16x2(h0, h1);
        WFl[l * 16384 + i] = pack_bf16x2(v0 - h0, v1 - h1);
    }
    if (tid < CCH) {
        int c = tid;
        const float* cw3 = cw + c * 384 + 256;
        const float* ewl = edge_w + l * (CCH * 5);
        const float* ebl = edge_b + l * CCH;
        float m0 = 0.f, m1 = 0.f, m2 = 0.f, m3 = 0.f, m4 = 0.f, m5 = 0.f;
        for (int k = 0; k < CCH; k++) {
            float w = cw3[k];
            m0 += w * ewl[k * 5 + 0];
            m1 += w * ewl[k * 5 + 1];
            m2 += w * ewl[k * 5 + 2];
            m3 += w * ewl[k * 5 + 3];
            m4 += w * ewl[k * 5 + 4];
            m5 += w * ebl[k];
        }
        float* Mp = g_M + l * (CCH * 6) + c * 6;
        Mp[0] = m0; Mp[1] = m1; Mp[2] = m2; Mp[3] = m3; Mp[4] = m4; Mp[5] = m5;
    }
}

// ---------------- GEMM via mma.sync bf16 (split, 3 terms) --------------------
// grid = 384 nodes x 4 mgroups; block 128 (4 warps: 2 mtiles x 4 nfrags each).
__global__ __launch_bounds__(128)
void gemm_mma_kernel(int l) {
    int tid = threadIdx.x, w = tid >> 5, lane = tid & 31;
    int node = blockIdx.x >> 2, mg = blockIdx.x & 3;
    int mt0 = mg * 4 + (w >> 1) * 2;       // this warp: mtiles mt0, mt0+1
    int nh = w & 1;                        // n-frags nh*4 .. nh*4+3
    int g = lane >> 2, t = lane & 3;

    const uint4* WAh = reinterpret_cast<const uint4*>(WFh);
    const uint4* WAl = reinterpret_cast<const uint4*>(WFl);
    const uint2* XB2h = reinterpret_cast<const uint2*>(XBh);
    const uint2* XB2l = reinterpret_cast<const uint2*>(XBl);

    float acc[2][4][4];
#pragma unroll
    for (int mi = 0; mi < 2; mi++)
#pragma unroll
        for (int nf = 0; nf < 4; nf++)
#pragma unroll
            for (int q = 0; q < 4; q++) acc[mi][nf][q] = 0.f;

#pragma unroll
    for (int ks = 0; ks < 8; ks++) {
        uint4 Ah[2], Al[2];
#pragma unroll
        for (int mi = 0; mi < 2; mi++) {
            int ai = ((l * 16 + mt0 + mi) * 8 + ks) * 32 + lane;
            Ah[mi] = WAh[ai];
            Al[mi] = WAl[ai];
        }
        uint2 Bh[4], Bl[4];
#pragma unroll
        for (int nf = 0; nf < 4; nf++) {
            int bi = ((node * 8 + ks) * 8 + nh * 4 + nf) * 32 + lane;
            Bh[nf] = XB2h[bi];
            Bl[nf] = XB2l[bi];
        }
#pragma unroll
        for (int mi = 0; mi < 2; mi++)
#pragma unroll
            for (int nf = 0; nf < 4; nf++) {
                mma16816(acc[mi][nf], Ah[mi], Bh[nf]);
                mma16816(acc[mi][nf], Ah[mi], Bl[nf]);
                mma16816(acc[mi][nf], Al[mi], Bh[nf]);
            }
    }

#pragma unroll
    for (int mi = 0; mi < 2; mi++)
#pragma unroll
        for (int nf = 0; nf < 4; nf++) {
            int m = (mt0 + mi) * 16 + g;
            int h0 = (nh * 4 + nf) * 8 + 2 * t;
            if (h0 < HEIGHT) {
                size_t base = ((size_t)node * 2 + (m >> 7)) * NODE_SZ;
                float* p0 = g_y + base + (m & 127) * HEIGHT + h0;
                *(float2*)p0 = make_float2(acc[mi][nf][0], acc[mi][nf][1]);
                float* p1 = g_y + base + ((m + 8) & 127) * HEIGHT + h0;
                *(float2*)p1 = make_float2(acc[mi][nf][2], acc[mi][nf][3]);
            }
        }
}

// ---------------- edge(l): per-dst CTA, 512 threads ---------------------------
__global__ __launch_bounds__(512, 2)
void edge_kernel(const float* __restrict__ ea,
                 const float* __restrict__ lng,
                 const float* __restrict__ lnb,
                 const int* __restrict__ ei,
                 float* __restrict__ dout, int l) {
    extern __shared__ float sm[];
    float* es_all = sm + ES_OFF;
    __shared__ float red[32];

    int n = blockIdx.x, tid = threadIdx.x;
    const float* gl = lng + l * NODE_SZ;
    const float* bl = lnb + l * NODE_SZ;
    int deg = g_deg[n];

    {
        int s0 = ei[g_nbr[n * 16]];
        prefetch_node(sm, g_y + (size_t)(2 * s0 + 1) * NODE_SZ, tid);
    }

    const float* yan = g_y + (size_t)(2 * n) * NODE_SZ;
    float ya[15], acc[15];
#pragma unroll
    for (int it = 0; it < 15; it++) {
        ya[it] = yan[tid + (it << 9)];
        acc[it] = 0.f;
    }
    for (int idx = tid; idx < deg * CCH; idx += 512) {
        int j = idx >> 7, c = idx & 127;
        int e = g_nbr[n * 16 + j];
        const float* Mp = g_M + l * (CCH * 6) + c * 6;
        const float* eap = ea + e * 5;
        es_all[idx] = fmaf(Mp[0], eap[0], fmaf(Mp[1], eap[1], fmaf(Mp[2], eap[2],
                      fmaf(Mp[3], eap[3], fmaf(Mp[4], eap[4], Mp[5])))));
    }

    int bj = 0;
    for (int j = 0; j < deg; j++) {
        if (j + 1 < deg) {
            int s1i = ei[g_nbr[n * 16 + j + 1]];
            int bn = bj + 1; if (bn == 3) bn = 0;
            prefetch_node(sm + bn * NODE_SZ, g_y + (size_t)(2 * s1i + 1) * NODE_SZ, tid);
            asm volatile("cp.async.wait_group 1;");
        } else {
            asm volatile("cp.async.wait_group 0;");
        }
        __syncthreads();   // slot bj (+ es_all on j==0) visible; 3-slot ring safety

        const float* bf = sm + bj * NODE_SZ;
        const float* esj = es_all + j * CCH;
        float s1 = 0.f, s2 = 0.f;
#pragma unroll
        for (int it = 0; it < 15; it++) {
            int i = tid + (it << 9);
            float v = ya[it] + bf[i] + esj[i / HEIGHT];
            s1 += v;
            s2 += v * v;
        }
#pragma unroll
        for (int o = 16; o; o >>= 1) {
            s1 += __shfl_xor_sync(0xffffffffu, s1, o);
            s2 += __shfl_xor_sync(0xffffffffu, s2, o);
        }
        if ((tid & 31) == 0) { red[tid >> 5] = s1; red[16 + (tid >> 5)] = s2; }
        __syncthreads();
        float a = 0.f, b2 = 0.f;
#pragma unroll
        for (int w = 0; w < 16; w++) { a += red[w]; b2 += red[16 + w]; }
        float mu = a * (1.f / (float)NODE_SZ);
        float rs = rsqrtf(b2 * (1.f / (float)NODE_SZ) - mu * mu + 1e-5f);
#pragma unroll
        for (int it = 0; it < 15; it++) {
            int i = tid + (it << 9);
            float v = ya[it] + bf[i] + esj[i / HEIGHT];
            float o2 = (v - mu) * rs * gl[i] + bl[i];
            acc[it] += fmaxf(o2, 0.f);
        }
        bj++; if (bj == 3) bj = 0;
    }

    if (l == 3) {
        float* on = dout + (size_t)n * NODE_SZ;
#pragma unroll
        for (int it = 0; it < 15; it++)
            on[tid + (it << 9)] = acc[it];
    } else {
        // smem-staged permutation: linear acc -> coalesced fragment stores
        __syncthreads();              // all ring-slot reads complete
        float* lin = sm;              // reuse ring slots (7680 floats)
#pragma unroll
        for (int it = 0; it < 15; it++)
            lin[tid + (it << 9)] = acc[it];
        __syncthreads();
        frag_store(lin, n, tid, 512);
    }
}

// ---------------- launch -----------------------------------------------------
extern "C" void kernel_launch(void* const* d_in, const int* in_sizes, int n_in,
                              void* d_out, int out_size) {
    const float* x   = (const float*)d_in[0];
    const float* ea  = (const float*)d_in[1];
    const float* ew  = (const float*)d_in[2];
    const float* eb  = (const float*)d_in[3];
    const float* cw  = (const float*)d_in[4];
    const float* lng = (const float*)d_in[5];
    const float* lnb = (const float*)d_in[6];
    const int*   ei  = (const int*)d_in[7];
    float* out = (float*)d_out;
    int E = in_sizes[7] / 2;

    cudaFuncSetAttribute(edge_kernel, cudaFuncAttributeMaxDynamicSharedMemorySize, DYN_SMEM);

    setup_kernel<<<5 + N_NODES, 384>>>(ei, E, cw, ew, eb, x);
    for (int l = 0; l < N_LAYERS; l++) {
        gemm_mma_kernel<<<N_NODES * 4, 128>>>(l);
        edge_kernel<<<N_NODES, 512, DYN_SMEM>>>(ea, lng, lnb, ei, out, l);
    }
}